// round 4
// baseline (speedup 1.0000x reference)
#include <cuda_runtime.h>
#include <cuda_bf16.h>
#include <cstdint>

#define BB 8
#define NN 2000
#define EE 20
#define HH 128
#define TNODES 4
#define TROWS 80                 // 4 nodes * 20 edges per CTA tile
#define NTILES 4000              // 16000 nodes / 4

// kB smem layout (bytes)
#define SWH_OFF   0              // We hi bf16 swizzled: 128 rows * 256B = 32768
#define SWL_OFF   32768          // We lo
#define SLOG_OFF  0              // logits 80x132 fp32 = 42240 (aliases We after B-hoist)
#define LSTRIDE   132
#define SA_OFF    65536          // A bf16 double buffer: 2 * 40960
#define ABUF_B    40960          // hi (20480) + lo (20480)
#define ALO       20480
#define SSTAGE    147456         // fp32 staging for next tile: 40960
#define SIDX_OFF  188416         // 80 ints
#define SMEMB     188800

__device__ float g_Vx[BB * NN * HH];

typedef unsigned long long u64;

// ---------------------------------------------------------------- helpers
__device__ __forceinline__ u64 ffma2(u64 a, u64 b, u64 c) {
    u64 d;
    asm("fma.rn.f32x2 %0, %1, %2, %3;" : "=l"(d) : "l"(a), "l"(b), "l"(c));
    return d;
}
__device__ __forceinline__ float2 unpack2(u64 v) {
    float2 r;
    asm("mov.b64 {%0, %1}, %2;" : "=f"(r.x), "=f"(r.y) : "l"(v));
    return r;
}
__device__ __forceinline__ uint32_t smem_u32(const void* p) {
    uint32_t a;
    asm("{ .reg .u64 t; cvta.to.shared.u64 t, %1; cvt.u32.u64 %0, t; }" : "=r"(a) : "l"(p));
    return a;
}
// pack two fp32 into bf16x2: low half = bf16(first), high half = bf16(second)
__device__ __forceinline__ uint32_t pack_bf16(float lo, float hi) {
    uint32_t r;
    asm("cvt.rn.bf16x2.f32 %0, %1, %2;" : "=r"(r) : "f"(hi), "f"(lo));
    return r;
}
__device__ __forceinline__ void ldsm4(uint32_t addr, uint32_t* r) {
    asm volatile("ldmatrix.sync.aligned.m8n8.x4.shared.b16 {%0,%1,%2,%3}, [%4];"
                 : "=r"(r[0]), "=r"(r[1]), "=r"(r[2]), "=r"(r[3]) : "r"(addr));
}
__device__ __forceinline__ void ldsm2t(uint32_t addr, uint32_t* r) {
    asm volatile("ldmatrix.sync.aligned.m8n8.x2.trans.shared.b16 {%0,%1}, [%2];"
                 : "=r"(r[0]), "=r"(r[1]) : "r"(addr));
}
__device__ __forceinline__ void mma16816(float* d, const uint32_t* a, uint32_t b0, uint32_t b1) {
    asm volatile("mma.sync.aligned.m16n8k16.row.col.f32.bf16.bf16.f32 "
                 "{%0,%1,%2,%3}, {%4,%5,%6,%7}, {%8,%9}, {%0,%1,%2,%3};"
                 : "+f"(d[0]), "+f"(d[1]), "+f"(d[2]), "+f"(d[3])
                 : "r"(a[0]), "r"(a[1]), "r"(a[2]), "r"(a[3]), "r"(b0), "r"(b1));
}
__device__ __forceinline__ void cpasync16(uint32_t saddr, const void* g) {
    asm volatile("cp.async.cg.shared.global [%0], [%1], 16;" :: "r"(saddr), "l"(g));
}

// Convert one float4 (4 consecutive k/col values) into bf16 hi/lo and store
// into swizzled 256B-row layout. ch4 = float4 index within the 128-wide tile.
__device__ __forceinline__ void cvtStore4(char* dh, char* dl, int ch4, float4 v) {
    int row = ch4 >> 5;                 // 32 float4 per 128-elem row
    int c16 = (ch4 & 31) >> 1;          // 16B chunk 0..15
    int half = (ch4 & 1) << 3;          // 0 or 8 bytes
    uint32_t sw = ((uint32_t)row << 8) + (((uint32_t)(c16 ^ (row & 7))) << 4) + half;
    uint32_t h0 = pack_bf16(v.x, v.y);
    uint32_t h1 = pack_bf16(v.z, v.w);
    uint32_t l0 = pack_bf16(v.x - __uint_as_float(h0 << 16),
                            v.y - __uint_as_float(h0 & 0xffff0000u));
    uint32_t l1 = pack_bf16(v.z - __uint_as_float(h1 << 16),
                            v.w - __uint_as_float(h1 & 0xffff0000u));
    *(uint2*)(dh + sw) = make_uint2(h0, h1);
    *(uint2*)(dl + sw) = make_uint2(l0, l1);
}

// ---------------------------------------------------------------------------
// Kernel A: Ux = x@Wu + bu -> out ;  Vx = x@Wv + bv -> g_Vx   (512 threads)
// ---------------------------------------------------------------------------
__global__ void __launch_bounds__(512, 1) kA(
    const float* __restrict__ x, const float* __restrict__ Wu,
    const float* __restrict__ bu, const float* __restrict__ Wv,
    const float* __restrict__ bv, float* __restrict__ out)
{
    extern __shared__ __align__(1024) float smA[];
    float* sWuP = smA;              // 16384 floats, pair-interleaved over k
    float* sWvP = smA + 16384;
    float* sx   = smA + 32768;      // 32 * 128 floats
    const int tid = threadIdx.x;

    for (int idx = tid; idx < 8192; idx += 512) {
        int kp = idx >> 7, j = idx & 127;
        sWuP[2 * idx]     = Wu[(2 * kp) * HH + j];
        sWuP[2 * idx + 1] = Wu[(2 * kp + 1) * HH + j];
        sWvP[2 * idx]     = Wv[(2 * kp) * HH + j];
        sWvP[2 * idx + 1] = Wv[(2 * kp + 1) * HH + j];
    }
    const int quarter = tid >> 7;   // 0..3, 8 rows each
    const int j = tid & 127;
    const float buj = bu[j];
    const float bvj = bv[j];
    const u64* wU = (const u64*)sWuP;
    const u64* wV = (const u64*)sWvP;
    __syncthreads();

    const int nGroups = (BB * NN) / 32;   // 500
    for (int g = blockIdx.x; g < nGroups; g += gridDim.x) {
        const float4* xs = (const float4*)(x + (size_t)g * 32 * HH);
        float4* sx4 = (float4*)sx;
        sx4[tid] = xs[tid];
        sx4[tid + 512] = xs[tid + 512];
        __syncthreads();

        u64 aU[8], aV[8];
        #pragma unroll
        for (int r = 0; r < 8; r++) { aU[r] = 0ull; aV[r] = 0ull; }
        const float* xr = sx + quarter * 8 * HH;
        #pragma unroll 4
        for (int kt = 0; kt < 32; kt++) {
            u64 wu0 = wU[(2 * kt) * HH + j];
            u64 wu1 = wU[(2 * kt + 1) * HH + j];
            u64 wv0 = wV[(2 * kt) * HH + j];
            u64 wv1 = wV[(2 * kt + 1) * HH + j];
            #pragma unroll
            for (int r = 0; r < 8; r++) {
                ulonglong2 xv = *(const ulonglong2*)(xr + r * HH + kt * 4);
                aU[r] = ffma2(xv.x, wu0, aU[r]);
                aU[r] = ffma2(xv.y, wu1, aU[r]);
                aV[r] = ffma2(xv.x, wv0, aV[r]);
                aV[r] = ffma2(xv.y, wv1, aV[r]);
            }
        }
        #pragma unroll
        for (int r = 0; r < 8; r++) {
            int row = g * 32 + quarter * 8 + r;
            float2 pu = unpack2(aU[r]);
            float2 pv = unpack2(aV[r]);
            out[(size_t)row * HH + j]  = pu.x + pu.y + buj;
            g_Vx[(size_t)row * HH + j] = pv.x + pv.y + bvj;
        }
        __syncthreads();
    }
}

// ---------------------------------------------------------------------------
// Kernel B: logits via mma.sync bf16 3-term split, B-regs hoisted, cp.async
// pipeline, softmax + gather epilogue. 512 threads / 16 warps, n8 per warp.
// ---------------------------------------------------------------------------
__global__ void __launch_bounds__(512, 1) kB(
    const float* __restrict__ e, const float* __restrict__ We,
    const int* __restrict__ edge_index, float* __restrict__ out)
{
    extern __shared__ __align__(1024) char smem[];
    const uint32_t sb = smem_u32(smem);
    float* sLog = (float*)(smem + SLOG_OFF);
    int*   sIdx = (int*)(smem + SIDX_OFF);
    const int tid = threadIdx.x;
    const int w = tid >> 5;          // 0..15, owns n-cols [8w, 8w+8)
    const int l = tid & 31;

    // ---- Build We hi/lo bf16 swizzled tiles (rows = k) ----
    #pragma unroll
    for (int q = 0; q < 8; q++) {
        int ch4 = tid + 512 * q;     // 0..4095 float4s of We
        float4 v = ((const float4*)We)[ch4];
        cvtStore4((char*)smem + SWH_OFF, (char*)smem + SWL_OFF, ch4, v);
    }
    __syncthreads();

    // ---- Hoist B (We) fragments into registers: k16 x n8 per ks ----
    uint32_t bh[8][2], bl[8][2];
    {
        const int l16 = l & 15;
        #pragma unroll
        for (int ks = 0; ks < 8; ks++) {
            int row = ks * 16 + l16;
            uint32_t off = ((uint32_t)row << 8) + (((uint32_t)(w ^ (row & 7))) << 4);
            ldsm2t(sb + SWH_OFF + off, bh[ks]);
            ldsm2t(sb + SWL_OFF + off, bl[ks]);
        }
    }

    // ---- Load first A tile directly (global -> cvt -> smem buf0) ----
    const int tile0 = blockIdx.x;
    if (tile0 < NTILES) {
        const float4* src = (const float4*)(e + (size_t)tile0 * TROWS * HH);
        char* dst = (char*)smem + SA_OFF;
        #pragma unroll
        for (int q = 0; q < 5; q++) {
            int ch4 = tid + 512 * q;     // 0..2559
            cvtStore4(dst, dst + ALO, ch4, src[ch4]);
        }
    }
    __syncthreads();   // covers: We build readers done, buf0 ready, hoist done

    const int lrow = (l & 7) + ((l >> 3) & 1) * 8;   // ldsm4 A row component
    const int lchk = l >> 4;                          // ldsm4 A chunk component

    int buf = 0;
    for (int tile = tile0; tile < NTILES; tile += gridDim.x) {
        const int ntile = tile + gridDim.x;
        const bool havenext = ntile < NTILES;

        // 1. async-stage next tile (fp32) under the mma loop
        if (havenext) {
            const char* src = (const char*)(e + (size_t)ntile * TROWS * HH);
            #pragma unroll
            for (int q = 0; q < 5; q++) {
                int ch4 = tid + 512 * q;
                cpasync16(sb + SSTAGE + ch4 * 16, src + ch4 * 16);
            }
            asm volatile("cp.async.commit_group;");
        }
        if (tid < TROWS) sIdx[tid] = edge_index[(size_t)tile * TROWS + tid];

        // 2. mma mainloop: D[80 x 128] over K=128, 3-term bf16 split
        float acc[5][4];
        #pragma unroll
        for (int mt = 0; mt < 5; mt++)
            #pragma unroll
            for (int q = 0; q < 4; q++) acc[mt][q] = 0.f;

        const uint32_t baseA = sb + SA_OFF + buf * ABUF_B;
        #pragma unroll
        for (int ks = 0; ks < 8; ks++) {
            uint32_t ah[5][4];
            #pragma unroll
            for (int mt = 0; mt < 5; mt++) {
                int row = mt * 16 + lrow;
                uint32_t off = ((uint32_t)row << 8) +
                               (((uint32_t)((ks * 2 + lchk) ^ (row & 7))) << 4);
                ldsm4(baseA + off, ah[mt]);
            }
            #pragma unroll
            for (int mt = 0; mt < 5; mt++) {
                mma16816(acc[mt], ah[mt], bh[ks][0], bh[ks][1]);   // eh*wh
                mma16816(acc[mt], ah[mt], bl[ks][0], bl[ks][1]);   // eh*wl
            }
            uint32_t al[5][4];
            #pragma unroll
            for (int mt = 0; mt < 5; mt++) {
                int row = mt * 16 + lrow;
                uint32_t off = ((uint32_t)row << 8) +
                               (((uint32_t)((ks * 2 + lchk) ^ (row & 7))) << 4);
                ldsm4(baseA + ALO + off, al[mt]);
            }
            #pragma unroll
            for (int mt = 0; mt < 5; mt++)
                mma16816(acc[mt], al[mt], bh[ks][0], bh[ks][1]);   // el*wh
        }

        // 3. D fragments -> logits smem
        #pragma unroll
        for (int mt = 0; mt < 5; mt++) {
            int r0 = mt * 16 + (l >> 2);
            int c0 = w * 8 + 2 * (l & 3);
            *(float2*)(sLog + r0 * LSTRIDE + c0) = make_float2(acc[mt][0], acc[mt][1]);
            *(float2*)(sLog + (r0 + 8) * LSTRIDE + c0) = make_float2(acc[mt][2], acc[mt][3]);
        }

        // 4. drain stage, cvt -> other A buffer (thread-private stage slots)
        if (havenext) {
            asm volatile("cp.async.wait_group 0;" ::: "memory");
            char* dst = (char*)smem + SA_OFF + (buf ^ 1) * ABUF_B;
            const float4* stg = (const float4*)(smem + SSTAGE);
            #pragma unroll
            for (int q = 0; q < 5; q++) {
                int ch4 = tid + 512 * q;
                cvtStore4(dst, dst + ALO, ch4, stg[ch4]);
            }
        }
        __syncthreads();

        // 5. epilogue: one (node, channel) per thread
        {
            const int tt = tid >> 7;          // node within tile
            const int j = tid & 127;          // channel
            float L[EE];
            #pragma unroll
            for (int i = 0; i < EE; i++)
                L[i] = sLog[(tt * EE + i) * LSTRIDE + j];
            float m = L[0];
            #pragma unroll
            for (int i = 1; i < EE; i++) m = fmaxf(m, L[i]);
            float s = 0.f;
            #pragma unroll
            for (int i = 0; i < EE; i++) {
                float ex = __expf(L[i] - m);
                L[i] = ex;
                s += ex;
            }
            const int node = tile * TNODES + tt;
            const int bbase = (node / NN) * NN;
            float accO = 0.f;
            #pragma unroll
            for (int i = 0; i < EE; i++) {
                int rr = sIdx[tt * EE + i];
                accO += L[i] * g_Vx[(size_t)(bbase + rr) * HH + j];
            }
            out[(size_t)node * HH + j] += accO * __fdividef(1.f, s);
        }
        __syncthreads();
        buf ^= 1;
    }
}

// ---------------------------------------------------------------------------
extern "C" void kernel_launch(void* const* d_in, const int* in_sizes, int n_in,
                              void* d_out, int out_size)
{
    const float* x          = (const float*)d_in[0];
    const float* e          = (const float*)d_in[1];
    const float* Wu         = (const float*)d_in[2];
    const float* bu         = (const float*)d_in[3];
    const float* Wv         = (const float*)d_in[4];
    const float* bv         = (const float*)d_in[5];
    const float* We         = (const float*)d_in[6];
    const int*   edge_index = (const int*)d_in[8];
    float* out = (float*)d_out;

    int sms = 148;
    cudaDeviceGetAttribute(&sms, cudaDevAttrMultiProcessorCount, 0);

    const int smemA = (16384 + 16384 + 4096) * 4;   // 147456 B
    cudaFuncSetAttribute(kA, cudaFuncAttributeMaxDynamicSharedMemorySize, smemA);
    cudaFuncSetAttribute(kB, cudaFuncAttributeMaxDynamicSharedMemorySize, SMEMB);

    kA<<<sms, 512, smemA>>>(x, Wu, bu, Wv, bv, out);
    kB<<<sms, 512, SMEMB>>>(e, We, edge_index, out);
}

// round 5
// speedup vs baseline: 1.1726x; 1.1726x over previous
#include <cuda_runtime.h>
#include <cuda_fp16.h>
#include <cstdint>

#define BB 8
#define NN 2000
#define EE 20
#define HH 128
#define TNODES 4
#define TROWS 80                 // 4 nodes * 20 edges per CTA tile
#define NTILES 4000              // 16000 nodes / 4

// kB smem layout (bytes)
#define SA_OFF    0              // A fp16 double buffer: 2 * 20480
#define ABUF_B    20480
#define STAGE_OFF 40960          // fp32 staging (also Wh build area): 40960
#define SLOG_OFF  81920          // logits 80x132 fp32 = 42240 (also Wl build area)
#define LSTRIDE   132
#define SIDX_OFF  124160         // 80 ints
#define SMEMB     124544

__device__ float g_Vx[BB * NN * HH];

typedef unsigned long long u64;

// ---------------------------------------------------------------- helpers
__device__ __forceinline__ u64 ffma2(u64 a, u64 b, u64 c) {
    u64 d;
    asm("fma.rn.f32x2 %0, %1, %2, %3;" : "=l"(d) : "l"(a), "l"(b), "l"(c));
    return d;
}
__device__ __forceinline__ float2 unpack2(u64 v) {
    float2 r;
    asm("mov.b64 {%0, %1}, %2;" : "=f"(r.x), "=f"(r.y) : "l"(v));
    return r;
}
__device__ __forceinline__ uint32_t smem_u32(const void* p) {
    uint32_t a;
    asm("{ .reg .u64 t; cvta.to.shared.u64 t, %1; cvt.u32.u64 %0, t; }" : "=r"(a) : "l"(p));
    return a;
}
// pack two fp32 -> fp16x2 (first arg -> low half)
__device__ __forceinline__ uint32_t pack_f16(float lo, float hi) {
    uint32_t r;
    asm("cvt.rn.f16x2.f32 %0, %1, %2;" : "=r"(r) : "f"(hi), "f"(lo));
    return r;
}
__device__ __forceinline__ float f16lo(uint32_t p) {
    float f;
    asm("{ .reg .b16 l, h; mov.b32 {l, h}, %1; cvt.f32.f16 %0, l; }" : "=f"(f) : "r"(p));
    return f;
}
__device__ __forceinline__ float f16hi(uint32_t p) {
    float f;
    asm("{ .reg .b16 l, h; mov.b32 {l, h}, %1; cvt.f32.f16 %0, h; }" : "=f"(f) : "r"(p));
    return f;
}
__device__ __forceinline__ void ldsm4(uint32_t addr, uint32_t* r) {
    asm volatile("ldmatrix.sync.aligned.m8n8.x4.shared.b16 {%0,%1,%2,%3}, [%4];"
                 : "=r"(r[0]), "=r"(r[1]), "=r"(r[2]), "=r"(r[3]) : "r"(addr));
}
__device__ __forceinline__ void ldsm4t(uint32_t addr, uint32_t* r) {
    asm volatile("ldmatrix.sync.aligned.m8n8.x4.trans.shared.b16 {%0,%1,%2,%3}, [%4];"
                 : "=r"(r[0]), "=r"(r[1]), "=r"(r[2]), "=r"(r[3]) : "r"(addr));
}
__device__ __forceinline__ void mma16816(float* d, const uint32_t* a, uint32_t b0, uint32_t b1) {
    asm volatile("mma.sync.aligned.m16n8k16.row.col.f32.f16.f16.f32 "
                 "{%0,%1,%2,%3}, {%4,%5,%6,%7}, {%8,%9}, {%0,%1,%2,%3};"
                 : "+f"(d[0]), "+f"(d[1]), "+f"(d[2]), "+f"(d[3])
                 : "r"(a[0]), "r"(a[1]), "r"(a[2]), "r"(a[3]), "r"(b0), "r"(b1));
}
__device__ __forceinline__ void cpasync16(uint32_t saddr, const void* g) {
    asm volatile("cp.async.cg.shared.global [%0], [%1], 16;" :: "r"(saddr), "l"(g));
}

// Convert float4 (4 consecutive k values) -> fp16, store to swizzled 256B-row
// layout. ch4 = float4 index within a 128-wide fp32 tile.
__device__ __forceinline__ void cvtStoreF16(char* dst, int ch4, float4 v) {
    int row = ch4 >> 5;                  // 32 float4 per 128-elem row
    int c4 = ch4 & 31;
    uint32_t sw = ((uint32_t)row << 8) + ((((uint32_t)(c4 >> 1)) ^ (row & 7)) << 4)
                + ((c4 & 1) << 3);
    uint32_t p0 = pack_f16(v.x, v.y);
    uint32_t p1 = pack_f16(v.z, v.w);
    *(uint2*)(dst + sw) = make_uint2(p0, p1);
}

// ---------------------------------------------------------------------------
// Kernel A: Ux = x@Wu + bu -> out ;  Vx = x@Wv + bv -> g_Vx  (round-3 version)
// ---------------------------------------------------------------------------
__global__ void __launch_bounds__(256, 1) kA(
    const float* __restrict__ x, const float* __restrict__ Wu,
    const float* __restrict__ bu, const float* __restrict__ Wv,
    const float* __restrict__ bv, float* __restrict__ out)
{
    extern __shared__ __align__(1024) float smA[];
    float* sWuP = smA;
    float* sWvP = smA + 16384;
    float* sx   = smA + 32768;      // 16 * 128
    const int tid = threadIdx.x;

    for (int idx = tid; idx < 8192; idx += 256) {
        int kp = idx >> 7, j = idx & 127;
        sWuP[2 * idx]     = Wu[(2 * kp) * HH + j];
        sWuP[2 * idx + 1] = Wu[(2 * kp + 1) * HH + j];
        sWvP[2 * idx]     = Wv[(2 * kp) * HH + j];
        sWvP[2 * idx + 1] = Wv[(2 * kp + 1) * HH + j];
    }
    const int half = tid >> 7;
    const int j = tid & 127;
    const float buj = bu[j];
    const float bvj = bv[j];
    const u64* wU = (const u64*)sWuP;
    const u64* wV = (const u64*)sWvP;
    __syncthreads();

    const int nGroups = (BB * NN) / 16;   // 1000
    for (int g = blockIdx.x; g < nGroups; g += gridDim.x) {
        const float4* xs = (const float4*)(x + (size_t)g * 16 * HH);
        float4* sx4 = (float4*)sx;
        sx4[tid] = xs[tid];
        sx4[tid + 256] = xs[tid + 256];
        __syncthreads();

        u64 aU[8], aV[8];
        #pragma unroll
        for (int r = 0; r < 8; r++) { aU[r] = 0ull; aV[r] = 0ull; }
        const float* xr = sx + half * 8 * HH;
        #pragma unroll 4
        for (int kt = 0; kt < 32; kt++) {
            u64 wu0 = wU[(2 * kt) * HH + j];
            u64 wu1 = wU[(2 * kt + 1) * HH + j];
            u64 wv0 = wV[(2 * kt) * HH + j];
            u64 wv1 = wV[(2 * kt + 1) * HH + j];
            #pragma unroll
            for (int r = 0; r < 8; r++) {
                ulonglong2 xv = *(const ulonglong2*)(xr + r * HH + kt * 4);
                aU[r] = ffma2(xv.x, wu0, aU[r]);
                aU[r] = ffma2(xv.y, wu1, aU[r]);
                aV[r] = ffma2(xv.x, wv0, aV[r]);
                aV[r] = ffma2(xv.y, wv1, aV[r]);
            }
        }
        #pragma unroll
        for (int r = 0; r < 8; r++) {
            int row = g * 16 + half * 8 + r;
            float2 pu = unpack2(aU[r]);
            float2 pv = unpack2(aV[r]);
            out[(size_t)row * HH + j]  = pu.x + pu.y + buj;
            g_Vx[(size_t)row * HH + j] = pv.x + pv.y + bvj;
        }
        __syncthreads();
    }
}

// ---------------------------------------------------------------------------
// Kernel B: logits = e @ We via fp16 mma, 2-term W split (e16*Wh + e16*Wl).
// 512 threads / 16 warps. Warp grid: m-group (w>>3): {tiles 0..2} / {3,4};
// n-columns: (w&7)*16. W fragments hoisted to registers (64 regs/warp).
// ---------------------------------------------------------------------------
__global__ void __launch_bounds__(512, 1) kB(
    const float* __restrict__ e, const float* __restrict__ We,
    const int* __restrict__ edge_index, float* __restrict__ out)
{
    extern __shared__ __align__(1024) char smem[];
    const uint32_t sb = smem_u32(smem);
    float* sLog = (float*)(smem + SLOG_OFF);
    int*   sIdx = (int*)(smem + SIDX_OFF);
    const int tid = threadIdx.x;
    const int w = tid >> 5;
    const int l = tid & 31;
    const int mg = w >> 3;           // 0: m-tiles 0..2, 1: m-tiles 3..4
    const int c = w & 7;             // n-cols [16c, 16c+16)
    const int mbase = mg * 3;

    // ---- Build Wh (stage area) and Wl (logits area) fp16 swizzled ----
    {
        char* dh = (char*)smem + STAGE_OFF;
        char* dl = (char*)smem + SLOG_OFF;
        #pragma unroll
        for (int q = 0; q < 8; q++) {
            int ch4 = tid + 512 * q;         // 0..4095
            float4 v = ((const float4*)We)[ch4];
            int row = ch4 >> 5, c4 = ch4 & 31;
            uint32_t sw = ((uint32_t)row << 8) +
                          ((((uint32_t)(c4 >> 1)) ^ (row & 7)) << 4) + ((c4 & 1) << 3);
            uint32_t h0 = pack_f16(v.x, v.y);
            uint32_t h1 = pack_f16(v.z, v.w);
            uint32_t l0 = pack_f16(v.x - f16lo(h0), v.y - f16hi(h0));
            uint32_t l1 = pack_f16(v.z - f16lo(h1), v.w - f16hi(h1));
            *(uint2*)(dh + sw) = make_uint2(h0, h1);
            *(uint2*)(dl + sw) = make_uint2(l0, l1);
        }
    }
    __syncthreads();

    // ---- Hoist W fragments: bh/bl[ks][4] covering n16 k16 per ks ----
    const int lrow = (l & 7) + ((l >> 3) & 1) * 8;
    const int lchk = l >> 4;
    uint32_t bh[8][4], bl[8][4];
    #pragma unroll
    for (int ks = 0; ks < 8; ks++) {
        int row = ks * 16 + lrow;
        uint32_t off = ((uint32_t)row << 8) + (((uint32_t)((c * 2 + lchk) ^ (row & 7))) << 4);
        ldsm4t(sb + STAGE_OFF + off, bh[ks]);
        ldsm4t(sb + SLOG_OFF + off, bl[ks]);
    }
    __syncthreads();   // all hoists done before stage/logits reuse

    // ---- Prologue: stage tile0, convert to A[0] ----
    const int tile0 = blockIdx.x;
    if (tile0 < NTILES) {
        const char* src = (const char*)(e + (size_t)tile0 * TROWS * HH);
        #pragma unroll
        for (int q = 0; q < 5; q++) {
            int ch4 = tid + 512 * q;
            cpasync16(sb + STAGE_OFF + ch4 * 16, src + ch4 * 16);
        }
        asm volatile("cp.async.commit_group;");
        asm volatile("cp.async.wait_group 0;" ::: "memory");
        __syncthreads();
        const float4* stg = (const float4*)(smem + STAGE_OFF);
        char* dst = (char*)smem + SA_OFF;
        #pragma unroll
        for (int q = 0; q < 5; q++) {
            int ch4 = tid + 512 * q;
            cvtStoreF16(dst, ch4, stg[ch4]);
        }
    }
    __syncthreads();

    int buf = 0;
    for (int tile = tile0; tile < NTILES; tile += gridDim.x) {
        const int ntile = tile + gridDim.x;
        const bool havenext = ntile < NTILES;

        // 1. stage next tile under the mma loop
        if (havenext) {
            const char* src = (const char*)(e + (size_t)ntile * TROWS * HH);
            #pragma unroll
            for (int q = 0; q < 5; q++) {
                int ch4 = tid + 512 * q;
                cpasync16(sb + STAGE_OFF + ch4 * 16, src + ch4 * 16);
            }
            asm volatile("cp.async.commit_group;");
        }
        if (tid < TROWS) sIdx[tid] = edge_index[(size_t)tile * TROWS + tid];

        // 2. mma mainloop
        float acc0[2][4], acc1[2][4], acc2[2][4];
        #pragma unroll
        for (int nt = 0; nt < 2; nt++)
            #pragma unroll
            for (int q = 0; q < 4; q++) { acc0[nt][q] = 0.f; acc1[nt][q] = 0.f; acc2[nt][q] = 0.f; }

        const uint32_t baseA = sb + SA_OFF + buf * ABUF_B;
        #pragma unroll
        for (int ks = 0; ks < 8; ks++) {
            uint32_t a0[4], a1[4], a2[4];
            {
                int row = (mbase + 0) * 16 + lrow;
                uint32_t off = ((uint32_t)row << 8) +
                               (((uint32_t)((ks * 2 + lchk) ^ (row & 7))) << 4);
                ldsm4(baseA + off, a0);
            }
            {
                int row = (mbase + 1) * 16 + lrow;
                uint32_t off = ((uint32_t)row << 8) +
                               (((uint32_t)((ks * 2 + lchk) ^ (row & 7))) << 4);
                ldsm4(baseA + off, a1);
            }
            if (mg == 0) {
                int row = 2 * 16 + lrow;
                uint32_t off = ((uint32_t)row << 8) +
                               (((uint32_t)((ks * 2 + lchk) ^ (row & 7))) << 4);
                ldsm4(baseA + off, a2);
            }
            mma16816(acc0[0], a0, bh[ks][0], bh[ks][1]);
            mma16816(acc0[1], a0, bh[ks][2], bh[ks][3]);
            mma16816(acc1[0], a1, bh[ks][0], bh[ks][1]);
            mma16816(acc1[1], a1, bh[ks][2], bh[ks][3]);
            mma16816(acc0[0], a0, bl[ks][0], bl[ks][1]);
            mma16816(acc0[1], a0, bl[ks][2], bl[ks][3]);
            mma16816(acc1[0], a1, bl[ks][0], bl[ks][1]);
            mma16816(acc1[1], a1, bl[ks][2], bl[ks][3]);
            if (mg == 0) {
                mma16816(acc2[0], a2, bh[ks][0], bh[ks][1]);
                mma16816(acc2[1], a2, bh[ks][2], bh[ks][3]);
                mma16816(acc2[0], a2, bl[ks][0], bl[ks][1]);
                mma16816(acc2[1], a2, bl[ks][2], bl[ks][3]);
            }
        }

        // 3. fragments -> logits smem
        #pragma unroll
        for (int nt = 0; nt < 2; nt++) {
            int c0 = c * 16 + nt * 8 + 2 * (l & 3);
            {
                int r0 = (mbase + 0) * 16 + (l >> 2);
                *(float2*)(sLog + r0 * LSTRIDE + c0) = make_float2(acc0[nt][0], acc0[nt][1]);
                *(float2*)(sLog + (r0 + 8) * LSTRIDE + c0) = make_float2(acc0[nt][2], acc0[nt][3]);
            }
            {
                int r0 = (mbase + 1) * 16 + (l >> 2);
                *(float2*)(sLog + r0 * LSTRIDE + c0) = make_float2(acc1[nt][0], acc1[nt][1]);
                *(float2*)(sLog + (r0 + 8) * LSTRIDE + c0) = make_float2(acc1[nt][2], acc1[nt][3]);
            }
            if (mg == 0) {
                int r0 = 2 * 16 + (l >> 2);
                *(float2*)(sLog + r0 * LSTRIDE + c0) = make_float2(acc2[nt][0], acc2[nt][1]);
                *(float2*)(sLog + (r0 + 8) * LSTRIDE + c0) = make_float2(acc2[nt][2], acc2[nt][3]);
            }
        }

        // 4. drain stage, convert into the other A buffer
        if (havenext) {
            asm volatile("cp.async.wait_group 0;" ::: "memory");
            char* dst = (char*)smem + SA_OFF + (buf ^ 1) * ABUF_B;
            const float4* stg = (const float4*)(smem + STAGE_OFF);
            #pragma unroll
            for (int q = 0; q < 5; q++) {
                int ch4 = tid + 512 * q;
                cvtStoreF16(dst, ch4, stg[ch4]);
            }
        }
        __syncthreads();

        // 5. epilogue: one (node, channel) per thread
        {
            const int tt = tid >> 7;
            const int j = tid & 127;
            float L[EE];
            #pragma unroll
            for (int i = 0; i < EE; i++)
                L[i] = sLog[(tt * EE + i) * LSTRIDE + j];
            float m = L[0];
            #pragma unroll
            for (int i = 1; i < EE; i++) m = fmaxf(m, L[i]);
            float s = 0.f;
            #pragma unroll
            for (int i = 0; i < EE; i++) {
                float ex = __expf(L[i] - m);
                L[i] = ex;
                s += ex;
            }
            const int node = tile * TNODES + tt;
            const int bbase = (node / NN) * NN;
            float accO = 0.f;
            #pragma unroll
            for (int i = 0; i < EE; i++) {
                int rr = sIdx[tt * EE + i];
                accO += L[i] * g_Vx[(size_t)(bbase + rr) * HH + j];
            }
            out[(size_t)node * HH + j] += accO * __fdividef(1.f, s);
        }
        __syncthreads();
        buf ^= 1;
    }
}

// ---------------------------------------------------------------------------
extern "C" void kernel_launch(void* const* d_in, const int* in_sizes, int n_in,
                              void* d_out, int out_size)
{
    const float* x          = (const float*)d_in[0];
    const float* e          = (const float*)d_in[1];
    const float* Wu         = (const float*)d_in[2];
    const float* bu         = (const float*)d_in[3];
    const float* Wv         = (const float*)d_in[4];
    const float* bv         = (const float*)d_in[5];
    const float* We         = (const float*)d_in[6];
    const int*   edge_index = (const int*)d_in[8];
    float* out = (float*)d_out;

    int sms = 148;
    cudaDeviceGetAttribute(&sms, cudaDevAttrMultiProcessorCount, 0);

    const int smemA = (16384 + 16384 + 2048) * 4;   // 139264 B
    cudaFuncSetAttribute(kA, cudaFuncAttributeMaxDynamicSharedMemorySize, smemA);
    cudaFuncSetAttribute(kB, cudaFuncAttributeMaxDynamicSharedMemorySize, SMEMB);

    kA<<<sms, 256, smemA>>>(x, Wu, bu, Wv, bv, out);
    kB<<<sms, 512, SMEMB>>>(e, We, edge_index, out);
}

// round 9
// speedup vs baseline: 1.6391x; 1.3979x over previous
#include <cuda_runtime.h>
#include <cuda_fp16.h>
#include <cstdint>

#define BB 8
#define NN 2000
#define EE 20
#define HH 128
#define TNODES 4
#define TROWS 80                 // 4 nodes * 20 edges per CTA tile
#define NTILES 4000              // 16000 nodes / 4

// kB smem layout (bytes). Stage (fp32 next-tile, 40960B) and logits
// (80x132 fp32 = 42240B) ALIAS the same region: stage is drained into the
// A-buffer before logits are written each tile.
#define SA_OFF    0              // A fp16 double buffer: 2 * 20480
#define ABUF_B    20480
#define ALIAS_OFF 40960          // stage / logits shared region (42240B)
#define LSTRIDE   132
#define SIDX_OFF  83200          // 80 ints
#define SMEMB     83584
// transient W-build areas (before the pipeline starts): WH at 0, WL at 32768

// kA smem layout
#define KA_SX 0                  // x fp16 swizzled 32768
#define KA_WH 32768              // W hi fp16 swizzled 32768
#define KA_WL 65536              // W lo fp16 swizzled 32768
#define KA_SMEM 98304

__device__ float g_Vx[BB * NN * HH];

// ---------------------------------------------------------------- helpers
__device__ __forceinline__ uint32_t smem_u32(const void* p) {
    uint32_t a;
    asm("{ .reg .u64 t; cvta.to.shared.u64 t, %1; cvt.u32.u64 %0, t; }" : "=r"(a) : "l"(p));
    return a;
}
// pack two fp32 -> fp16x2 (first arg -> low half)
__device__ __forceinline__ uint32_t pack_f16(float lo, float hi) {
    uint32_t r;
    asm("cvt.rn.f16x2.f32 %0, %1, %2;" : "=r"(r) : "f"(hi), "f"(lo));
    return r;
}
__device__ __forceinline__ float f16lo(uint32_t p) {
    float f;
    asm("{ .reg .b16 l, h; mov.b32 {l, h}, %1; cvt.f32.f16 %0, l; }" : "=f"(f) : "r"(p));
    return f;
}
__device__ __forceinline__ float f16hi(uint32_t p) {
    float f;
    asm("{ .reg .b16 l, h; mov.b32 {l, h}, %1; cvt.f32.f16 %0, h; }" : "=f"(f) : "r"(p));
    return f;
}
__device__ __forceinline__ void ldsm4(uint32_t addr, uint32_t* r) {
    asm volatile("ldmatrix.sync.aligned.m8n8.x4.shared.b16 {%0,%1,%2,%3}, [%4];"
                 : "=r"(r[0]), "=r"(r[1]), "=r"(r[2]), "=r"(r[3]) : "r"(addr));
}
__device__ __forceinline__ void ldsm4t(uint32_t addr, uint32_t* r) {
    asm volatile("ldmatrix.sync.aligned.m8n8.x4.trans.shared.b16 {%0,%1,%2,%3}, [%4];"
                 : "=r"(r[0]), "=r"(r[1]), "=r"(r[2]), "=r"(r[3]) : "r"(addr));
}
__device__ __forceinline__ void mma16816(float* d, const uint32_t* a, uint32_t b0, uint32_t b1) {
    asm volatile("mma.sync.aligned.m16n8k16.row.col.f32.f16.f16.f32 "
                 "{%0,%1,%2,%3}, {%4,%5,%6,%7}, {%8,%9}, {%0,%1,%2,%3};"
                 : "+f"(d[0]), "+f"(d[1]), "+f"(d[2]), "+f"(d[3])
                 : "r"(a[0]), "r"(a[1]), "r"(a[2]), "r"(a[3]), "r"(b0), "r"(b1));
}
__device__ __forceinline__ void cpasync16(uint32_t saddr, const void* g) {
    asm volatile("cp.async.cg.shared.global [%0], [%1], 16;" :: "r"(saddr), "l"(g));
}

// swizzled fp16 256B-row offset for float4-chunk index ch4 of a 128-wide tile
__device__ __forceinline__ uint32_t swoff(int ch4) {
    int row = ch4 >> 5, c4 = ch4 & 31;
    return ((uint32_t)row << 8) + ((((uint32_t)(c4 >> 1)) ^ (row & 7)) << 4) + ((c4 & 1) << 3);
}
// fp32 float4 -> fp16, stored swizzled
__device__ __forceinline__ void cvtStoreF16(char* dst, int ch4, float4 v) {
    uint32_t sw = swoff(ch4);
    *(uint2*)(dst + sw) = make_uint2(pack_f16(v.x, v.y), pack_f16(v.z, v.w));
}
// fp32 float4 -> fp16 hi + residual lo, stored swizzled
__device__ __forceinline__ void cvtStoreHL(char* dh, char* dl, int ch4, float4 v) {
    uint32_t sw = swoff(ch4);
    uint32_t h0 = pack_f16(v.x, v.y);
    uint32_t h1 = pack_f16(v.z, v.w);
    uint32_t l0 = pack_f16(v.x - f16lo(h0), v.y - f16hi(h0));
    uint32_t l1 = pack_f16(v.z - f16lo(h1), v.w - f16hi(h1));
    *(uint2*)(dh + sw) = make_uint2(h0, h1);
    *(uint2*)(dl + sw) = make_uint2(l0, l1);
}

// ---------------------------------------------------------------------------
// Kernel A (tensor-core): per CTA, 128 rows of x. Two passes:
//   pass 0: out  = x @ Wu + bu
//   pass 1: g_Vx = x @ Wv + bv
// 512 threads / 16 warps: mg = w>>3 owns m-tiles [4mg, 4mg+4), nc = w&7 owns
// n-cols [16nc, 16nc+16). fp16 2-term W split, x in fp16.
// ---------------------------------------------------------------------------
__global__ void __launch_bounds__(512, 1) kA(
    const float* __restrict__ x, const float* __restrict__ Wu,
    const float* __restrict__ bu, const float* __restrict__ Wv,
    const float* __restrict__ bv, float* __restrict__ out)
{
    extern __shared__ __align__(1024) char smem[];
    const uint32_t sb = smem_u32(smem);
    const int tid = threadIdx.x;
    const int w = tid >> 5;
    const int l = tid & 31;
    const int mg = w >> 3;
    const int nc = w & 7;
    const int lrow = (l & 7) + ((l >> 3) & 1) * 8;
    const int lchk = l >> 4;
    const size_t rowBase = (size_t)blockIdx.x * 128;

    // load x tile -> fp16 swizzled  (128x128 = 4096 float4s, 8 per thread)
    {
        const float4* src = (const float4*)(x + rowBase * HH);
        #pragma unroll
        for (int q = 0; q < 8; q++) {
            int ch4 = tid + 512 * q;
            cvtStoreF16((char*)smem + KA_SX, ch4, src[ch4]);
        }
    }

    #pragma unroll 1
    for (int pass = 0; pass < 2; pass++) {
        const float* W = pass ? Wv : Wu;
        const float* bias = pass ? bv : bu;
        // build W hi/lo  (4096 float4s, 8 per thread)
        #pragma unroll
        for (int q = 0; q < 8; q++) {
            int ch4 = tid + 512 * q;
            cvtStoreHL((char*)smem + KA_WH, (char*)smem + KA_WL, ch4,
                       ((const float4*)W)[ch4]);
        }
        __syncthreads();

        float acc[4][2][4];
        #pragma unroll
        for (int mt = 0; mt < 4; mt++)
            #pragma unroll
            for (int nt = 0; nt < 2; nt++)
                #pragma unroll
                for (int q = 0; q < 4; q++) acc[mt][nt][q] = 0.f;

        #pragma unroll
        for (int ks = 0; ks < 8; ks++) {
            uint32_t bh[4], bl[4];
            {
                int row = ks * 16 + lrow;
                uint32_t off = ((uint32_t)row << 8) +
                               (((uint32_t)((nc * 2 + lchk) ^ (row & 7))) << 4);
                ldsm4t(sb + KA_WH + off, bh);
                ldsm4t(sb + KA_WL + off, bl);
            }
            #pragma unroll
            for (int mt = 0; mt < 4; mt++) {
                uint32_t a[4];
                int row = mg * 64 + mt * 16 + lrow;
                uint32_t off = ((uint32_t)row << 8) +
                               (((uint32_t)((ks * 2 + lchk) ^ (row & 7))) << 4);
                ldsm4(sb + KA_SX + off, a);
                mma16816(acc[mt][0], a, bh[0], bh[1]);
                mma16816(acc[mt][1], a, bh[2], bh[3]);
                mma16816(acc[mt][0], a, bl[0], bl[1]);
                mma16816(acc[mt][1], a, bl[2], bl[3]);
            }
        }

        float* dst = pass ? g_Vx : out;
        #pragma unroll
        for (int nt = 0; nt < 2; nt++) {
            int c0 = nc * 16 + nt * 8 + 2 * (l & 3);
            float2 b2 = *(const float2*)(bias + c0);
            #pragma unroll
            for (int mt = 0; mt < 4; mt++) {
                int r0 = mg * 64 + mt * 16 + (l >> 2);
                *(float2*)(dst + (rowBase + r0) * HH + c0) =
                    make_float2(acc[mt][nt][0] + b2.x, acc[mt][nt][1] + b2.y);
                *(float2*)(dst + (rowBase + r0 + 8) * HH + c0) =
                    make_float2(acc[mt][nt][2] + b2.x, acc[mt][nt][3] + b2.y);
            }
        }
        __syncthreads();   // W area reads done before next pass overwrites
    }
}

// ---------------------------------------------------------------------------
// Kernel B: logits = e @ We via fp16 mma (2-term W split), softmax + gather.
// 256 threads / 8 warps, 2 CTAs per SM. Warp w owns n-cols [16w, 16w+16) and
// all 5 m-tiles. W fragments hoisted to registers.
// ---------------------------------------------------------------------------
__global__ void __launch_bounds__(256, 2) kB(
    const float* __restrict__ e, const float* __restrict__ We,
    const int* __restrict__ edge_index, float* __restrict__ out)
{
    extern __shared__ __align__(1024) char smem[];
    const uint32_t sb = smem_u32(smem);
    float* sLog = (float*)(smem + ALIAS_OFF);
    int*   sIdx = (int*)(smem + SIDX_OFF);
    const int tid = threadIdx.x;
    const int w = tid >> 5;
    const int l = tid & 31;
    const int lrow = (l & 7) + ((l >> 3) & 1) * 8;
    const int lchk = l >> 4;

    // ---- Build We hi/lo fp16 swizzled (transient: WH at 0, WL at 32768) ----
    // 128x128 = 4096 float4s, 16 per thread at 256 threads.
    #pragma unroll
    for (int q = 0; q < 16; q++) {
        int ch4 = tid + 256 * q;     // 0..4095
        cvtStoreHL((char*)smem, (char*)smem + 32768, ch4, ((const float4*)We)[ch4]);
    }
    __syncthreads();

    // ---- Hoist W fragments (n16 per warp, all K): 64 regs ----
    uint32_t bh[8][4], bl[8][4];
    #pragma unroll
    for (int ks = 0; ks < 8; ks++) {
        int row = ks * 16 + lrow;
        uint32_t off = ((uint32_t)row << 8) +
                       (((uint32_t)((w * 2 + lchk) ^ (row & 7))) << 4);
        ldsm4t(sb + off, bh[ks]);
        ldsm4t(sb + 32768 + off, bl[ks]);
    }
    __syncthreads();   // hoists done before regions are reused

    // ---- Prologue: stage tile0 -> A[0] ----
    const int tile0 = blockIdx.x;
    if (tile0 < NTILES) {
        const char* src = (const char*)(e + (size_t)tile0 * TROWS * HH);
        #pragma unroll
        for (int q = 0; q < 10; q++) {
            int ch4 = tid + 256 * q;
            cpasync16(sb + ALIAS_OFF + ch4 * 16, src + ch4 * 16);
        }
        asm volatile("cp.async.commit_group;");
        asm volatile("cp.async.wait_group 0;" ::: "memory");
        const float4* stg = (const float4*)(smem + ALIAS_OFF);
        #pragma unroll
        for (int q = 0; q < 10; q++) {
            int ch4 = tid + 256 * q;
            cvtStoreF16((char*)smem + SA_OFF, ch4, stg[ch4]);
        }
    }
    __syncthreads();

    int buf = 0;
    for (int tile = tile0; tile < NTILES; tile += gridDim.x) {
        const int ntile = tile + gridDim.x;
        const bool havenext = ntile < NTILES;

        // 1. stage next tile (fp32) into the alias region under the mma loop
        if (havenext) {
            const char* src = (const char*)(e + (size_t)ntile * TROWS * HH);
            #pragma unroll
            for (int q = 0; q < 10; q++) {
                int ch4 = tid + 256 * q;
                cpasync16(sb + ALIAS_OFF + ch4 * 16, src + ch4 * 16);
            }
            asm volatile("cp.async.commit_group;");
        }
        if (tid < TROWS) sIdx[tid] = edge_index[(size_t)tile * TROWS + tid];

        // 2. mma mainloop: D[80 x 128], 5 m-tiles per warp
        float acc[5][2][4];
        #pragma unroll
        for (int mt = 0; mt < 5; mt++)
            #pragma unroll
            for (int nt = 0; nt < 2; nt++)
                #pragma unroll
                for (int q = 0; q < 4; q++) acc[mt][nt][q] = 0.f;

        const uint32_t baseA = sb + SA_OFF + buf * ABUF_B;
        #pragma unroll
        for (int ks = 0; ks < 8; ks++) {
            #pragma unroll
            for (int mt = 0; mt < 5; mt++) {
                uint32_t a[4];
                int row = mt * 16 + lrow;
                uint32_t off = ((uint32_t)row << 8) +
                               (((uint32_t)((ks * 2 + lchk) ^ (row & 7))) << 4);
                ldsm4(baseA + off, a);
                mma16816(acc[mt][0], a, bh[ks][0], bh[ks][1]);
                mma16816(acc[mt][1], a, bh[ks][2], bh[ks][3]);
                mma16816(acc[mt][0], a, bl[ks][0], bl[ks][1]);
                mma16816(acc[mt][1], a, bl[ks][2], bl[ks][3]);
            }
        }

        // 3. drain stage into the other A buffer (frees the alias region)
        if (havenext) {
            asm volatile("cp.async.wait_group 0;" ::: "memory");
            char* dst = (char*)smem + SA_OFF + (buf ^ 1) * ABUF_B;
            const float4* stg = (const float4*)(smem + ALIAS_OFF);
            #pragma unroll
            for (int q = 0; q < 10; q++) {
                int ch4 = tid + 256 * q;
                cvtStoreF16(dst, ch4, stg[ch4]);
            }
        }
        __syncthreads();

        // 4. fragments -> logits (alias region, now free)
        #pragma unroll
        for (int mt = 0; mt < 5; mt++)
            #pragma unroll
            for (int nt = 0; nt < 2; nt++) {
                int r0 = mt * 16 + (l >> 2);
                int c0 = w * 16 + nt * 8 + 2 * (l & 3);
                *(float2*)(sLog + r0 * LSTRIDE + c0) =
                    make_float2(acc[mt][nt][0], acc[mt][nt][1]);
                *(float2*)(sLog + (r0 + 8) * LSTRIDE + c0) =
                    make_float2(acc[mt][nt][2], acc[mt][nt][3]);
            }
        __syncthreads();

        // 5. epilogue: softmax over 20 edges + gather; 2 (node,ch) per thread
        {
            const int j = tid & 127;
            #pragma unroll
            for (int h = 0; h < 2; h++) {
                const int tt = (tid >> 7) + 2 * h;
                float L[EE];
                #pragma unroll
                for (int i = 0; i < EE; i++)
                    L[i] = sLog[(tt * EE + i) * LSTRIDE + j];
                float m = L[0];
                #pragma unroll
                for (int i = 1; i < EE; i++) m = fmaxf(m, L[i]);
                float s = 0.f;
                #pragma unroll
                for (int i = 0; i < EE; i++) {
                    float ex = __expf(L[i] - m);
                    L[i] = ex;
                    s += ex;
                }
                const int node = tile * TNODES + tt;
                const int bbase = (node / NN) * NN;
                float accO = 0.f;
                #pragma unroll
                for (int i = 0; i < EE; i++) {
                    int rr = sIdx[tt * EE + i];
                    accO += L[i] * g_Vx[(size_t)(bbase + rr) * HH + j];
                }
                out[(size_t)node * HH + j] += accO * __fdividef(1.f, s);
            }
        }
        __syncthreads();
        buf ^= 1;
    }
}

// ---------------------------------------------------------------------------
extern "C" void kernel_launch(void* const* d_in, const int* in_sizes, int n_in,
                              void* d_out, int out_size)
{
    const float* x          = (const float*)d_in[0];
    const float* e          = (const float*)d_in[1];
    const float* Wu         = (const float*)d_in[2];
    const float* bu         = (const float*)d_in[3];
    const float* Wv         = (const float*)d_in[4];
    const float* bv         = (const float*)d_in[5];
    const float* We         = (const float*)d_in[6];
    const int*   edge_index = (const int*)d_in[8];
    float* out = (float*)d_out;

    int sms = 148;
    cudaDeviceGetAttribute(&sms, cudaDevAttrMultiProcessorCount, 0);

    cudaFuncSetAttribute(kA, cudaFuncAttributeMaxDynamicSharedMemorySize, KA_SMEM);
    cudaFuncSetAttribute(kB, cudaFuncAttributeMaxDynamicSharedMemorySize, SMEMB);

    kA<<<(BB * NN) / 128, 512, KA_SMEM>>>(x, Wu, bu, Wv, bv, out);
    kB<<<2 * sms, 256, SMEMB>>>(e, We, edge_index, out);
}

// round 11
// speedup vs baseline: 2.0929x; 1.2768x over previous
#include <cuda_runtime.h>
#include <cuda_fp16.h>
#include <cstdint>

#define BB 8
#define NN 2000
#define EE 20
#define HH 128
#define TNODES 4
#define TROWS 80                 // 4 nodes * 20 edges per CTA tile
#define NTILES 4000              // 16000 nodes / 4

// kB smem layout (bytes). Stage (fp32 next-tile, 40960B) and logits
// (80x132 fp32 = 42240B) ALIAS the same region: stage is drained into the
// A-buffer before logits are written each tile.
#define SA_OFF    0              // A fp16 double buffer: 2 * 20480
#define ABUF_B    20480
#define ALIAS_OFF 40960          // stage / logits shared region (42240B)
#define LSTRIDE   132
#define SIDX_OFF  83200          // 80 ints
#define SMEMB     83584
// transient W-build area (before the pipeline starts): WH at 0

// kA smem layout
#define KA_SX 0                  // x fp16 swizzled 32768
#define KA_WH 32768              // W hi fp16 swizzled 32768
#define KA_WL 65536              // W lo fp16 swizzled 32768
#define KA_SMEM 98304

__device__ float g_Vx[BB * NN * HH];

// ---------------------------------------------------------------- helpers
__device__ __forceinline__ uint32_t smem_u32(const void* p) {
    uint32_t a;
    asm("{ .reg .u64 t; cvta.to.shared.u64 t, %1; cvt.u32.u64 %0, t; }" : "=r"(a) : "l"(p));
    return a;
}
// pack two fp32 -> fp16x2 (first arg -> low half)
__device__ __forceinline__ uint32_t pack_f16(float lo, float hi) {
    uint32_t r;
    asm("cvt.rn.f16x2.f32 %0, %1, %2;" : "=r"(r) : "f"(hi), "f"(lo));
    return r;
}
__device__ __forceinline__ float f16lo(uint32_t p) {
    float f;
    asm("{ .reg .b16 l, h; mov.b32 {l, h}, %1; cvt.f32.f16 %0, l; }" : "=f"(f) : "r"(p));
    return f;
}
__device__ __forceinline__ float f16hi(uint32_t p) {
    float f;
    asm("{ .reg .b16 l, h; mov.b32 {l, h}, %1; cvt.f32.f16 %0, h; }" : "=f"(f) : "r"(p));
    return f;
}
__device__ __forceinline__ void ldsm4(uint32_t addr, uint32_t* r) {
    asm volatile("ldmatrix.sync.aligned.m8n8.x4.shared.b16 {%0,%1,%2,%3}, [%4];"
                 : "=r"(r[0]), "=r"(r[1]), "=r"(r[2]), "=r"(r[3]) : "r"(addr));
}
__device__ __forceinline__ void ldsm4t(uint32_t addr, uint32_t* r) {
    asm volatile("ldmatrix.sync.aligned.m8n8.x4.trans.shared.b16 {%0,%1,%2,%3}, [%4];"
                 : "=r"(r[0]), "=r"(r[1]), "=r"(r[2]), "=r"(r[3]) : "r"(addr));
}
__device__ __forceinline__ void mma16816(float* d, const uint32_t* a, uint32_t b0, uint32_t b1) {
    asm volatile("mma.sync.aligned.m16n8k16.row.col.f32.f16.f16.f32 "
                 "{%0,%1,%2,%3}, {%4,%5,%6,%7}, {%8,%9}, {%0,%1,%2,%3};"
                 : "+f"(d[0]), "+f"(d[1]), "+f"(d[2]), "+f"(d[3])
                 : "r"(a[0]), "r"(a[1]), "r"(a[2]), "r"(a[3]), "r"(b0), "r"(b1));
}
__device__ __forceinline__ void cpasync16(uint32_t saddr, const void* g) {
    asm volatile("cp.async.cg.shared.global [%0], [%1], 16;" :: "r"(saddr), "l"(g));
}

// swizzled fp16 256B-row offset for float4-chunk index ch4 of a 128-wide tile
__device__ __forceinline__ uint32_t swoff(int ch4) {
    int row = ch4 >> 5, c4 = ch4 & 31;
    return ((uint32_t)row << 8) + ((((uint32_t)(c4 >> 1)) ^ (row & 7)) << 4) + ((c4 & 1) << 3);
}
// fp32 float4 -> fp16, stored swizzled
__device__ __forceinline__ void cvtStoreF16(char* dst, int ch4, float4 v) {
    uint32_t sw = swoff(ch4);
    *(uint2*)(dst + sw) = make_uint2(pack_f16(v.x, v.y), pack_f16(v.z, v.w));
}
// fp32 float4 -> fp16 hi + residual lo, stored swizzled
__device__ __forceinline__ void cvtStoreHL(char* dh, char* dl, int ch4, float4 v) {
    uint32_t sw = swoff(ch4);
    uint32_t h0 = pack_f16(v.x, v.y);
    uint32_t h1 = pack_f16(v.z, v.w);
    uint32_t l0 = pack_f16(v.x - f16lo(h0), v.y - f16hi(h0));
    uint32_t l1 = pack_f16(v.z - f16lo(h1), v.w - f16hi(h1));
    *(uint2*)(dh + sw) = make_uint2(h0, h1);
    *(uint2*)(dl + sw) = make_uint2(l0, l1);
}

// ---------------------------------------------------------------------------
// Kernel A (tensor-core): per CTA, 128 rows of x. Two passes:
//   pass 0: out  = x @ Wu + bu
//   pass 1: g_Vx = x @ Wv + bv
// 512 threads / 16 warps. fp16 2-term W split (kept: kA is cheap; error budget
// spent in kB instead), x in fp16.
// ---------------------------------------------------------------------------
__global__ void __launch_bounds__(512, 1) kA(
    const float* __restrict__ x, const float* __restrict__ Wu,
    const float* __restrict__ bu, const float* __restrict__ Wv,
    const float* __restrict__ bv, float* __restrict__ out)
{
    extern __shared__ __align__(1024) char smem[];
    const uint32_t sb = smem_u32(smem);
    const int tid = threadIdx.x;
    const int w = tid >> 5;
    const int l = tid & 31;
    const int mg = w >> 3;
    const int nc = w & 7;
    const int lrow = (l & 7) + ((l >> 3) & 1) * 8;
    const int lchk = l >> 4;
    const size_t rowBase = (size_t)blockIdx.x * 128;

    // load x tile -> fp16 swizzled  (128x128 = 4096 float4s, 8 per thread)
    {
        const float4* src = (const float4*)(x + rowBase * HH);
        #pragma unroll
        for (int q = 0; q < 8; q++) {
            int ch4 = tid + 512 * q;
            cvtStoreF16((char*)smem + KA_SX, ch4, src[ch4]);
        }
    }

    #pragma unroll 1
    for (int pass = 0; pass < 2; pass++) {
        const float* W = pass ? Wv : Wu;
        const float* bias = pass ? bv : bu;
        // build W hi/lo  (4096 float4s, 8 per thread)
        #pragma unroll
        for (int q = 0; q < 8; q++) {
            int ch4 = tid + 512 * q;
            cvtStoreHL((char*)smem + KA_WH, (char*)smem + KA_WL, ch4,
                       ((const float4*)W)[ch4]);
        }
        __syncthreads();

        float acc[4][2][4];
        #pragma unroll
        for (int mt = 0; mt < 4; mt++)
            #pragma unroll
            for (int nt = 0; nt < 2; nt++)
                #pragma unroll
                for (int q = 0; q < 4; q++) acc[mt][nt][q] = 0.f;

        #pragma unroll
        for (int ks = 0; ks < 8; ks++) {
            uint32_t bh[4], bl[4];
            {
                int row = ks * 16 + lrow;
                uint32_t off = ((uint32_t)row << 8) +
                               (((uint32_t)((nc * 2 + lchk) ^ (row & 7))) << 4);
                ldsm4t(sb + KA_WH + off, bh);
                ldsm4t(sb + KA_WL + off, bl);
            }
            #pragma unroll
            for (int mt = 0; mt < 4; mt++) {
                uint32_t a[4];
                int row = mg * 64 + mt * 16 + lrow;
                uint32_t off = ((uint32_t)row << 8) +
                               (((uint32_t)((ks * 2 + lchk) ^ (row & 7))) << 4);
                ldsm4(sb + KA_SX + off, a);
                mma16816(acc[mt][0], a, bh[0], bh[1]);
                mma16816(acc[mt][1], a, bh[2], bh[3]);
                mma16816(acc[mt][0], a, bl[0], bl[1]);
                mma16816(acc[mt][1], a, bl[2], bl[3]);
            }
        }

        float* dst = pass ? g_Vx : out;
        #pragma unroll
        for (int nt = 0; nt < 2; nt++) {
            int c0 = nc * 16 + nt * 8 + 2 * (l & 3);
            float2 b2 = *(const float2*)(bias + c0);
            #pragma unroll
            for (int mt = 0; mt < 4; mt++) {
                int r0 = mg * 64 + mt * 16 + (l >> 2);
                *(float2*)(dst + (rowBase + r0) * HH + c0) =
                    make_float2(acc[mt][nt][0] + b2.x, acc[mt][nt][1] + b2.y);
                *(float2*)(dst + (rowBase + r0 + 8) * HH + c0) =
                    make_float2(acc[mt][nt][2] + b2.x, acc[mt][nt][3] + b2.y);
            }
        }
        __syncthreads();   // W area reads done before next pass overwrites
    }
}

// ---------------------------------------------------------------------------
// Kernel B: logits = e16 @ We16 via fp16 mma, SINGLE-term W (error analysis:
// e's fp16 rounding already dominates; dropping Wl adds ~sqrt(2) error, total
// ~3e-4 << 1e-3). Softmax + gather epilogue. 256 threads / 8 warps,
// 2 CTAs/SM. Warp w owns n-cols [16w, 16w+16), all 5 m-tiles. W in registers.
// ---------------------------------------------------------------------------
__global__ void __launch_bounds__(256, 2) kB(
    const float* __restrict__ e, const float* __restrict__ We,
    const int* __restrict__ edge_index, float* __restrict__ out)
{
    extern __shared__ __align__(1024) char smem[];
    const uint32_t sb = smem_u32(smem);
    float* sLog = (float*)(smem + ALIAS_OFF);
    int*   sIdx = (int*)(smem + SIDX_OFF);
    const int tid = threadIdx.x;
    const int w = tid >> 5;
    const int l = tid & 31;
    const int lrow = (l & 7) + ((l >> 3) & 1) * 8;
    const int lchk = l >> 4;

    // ---- Build We (hi only) fp16 swizzled at offset 0 (transient) ----
    // 128x128 = 4096 float4s, 16 per thread at 256 threads.
    #pragma unroll
    for (int q = 0; q < 16; q++) {
        int ch4 = tid + 256 * q;     // 0..4095
        cvtStoreF16((char*)smem, ch4, ((const float4*)We)[ch4]);
    }
    __syncthreads();

    // ---- Hoist W fragments (n16 per warp, all K): 32 regs ----
    uint32_t bh[8][4];
    #pragma unroll
    for (int ks = 0; ks < 8; ks++) {
        int row = ks * 16 + lrow;
        uint32_t off = ((uint32_t)row << 8) +
                       (((uint32_t)((w * 2 + lchk) ^ (row & 7))) << 4);
        ldsm4t(sb + off, bh[ks]);
    }
    __syncthreads();   // hoists done before region is reused

    // ---- Prologue: stage tile0 -> A[0] ----
    const int tile0 = blockIdx.x;
    if (tile0 < NTILES) {
        const char* src = (const char*)(e + (size_t)tile0 * TROWS * HH);
        #pragma unroll
        for (int q = 0; q < 10; q++) {
            int ch4 = tid + 256 * q;
            cpasync16(sb + ALIAS_OFF + ch4 * 16, src + ch4 * 16);
        }
        asm volatile("cp.async.commit_group;");
        asm volatile("cp.async.wait_group 0;" ::: "memory");
        const float4* stg = (const float4*)(smem + ALIAS_OFF);
        #pragma unroll
        for (int q = 0; q < 10; q++) {
            int ch4 = tid + 256 * q;
            cvtStoreF16((char*)smem + SA_OFF, ch4, stg[ch4]);
        }
    }
    __syncthreads();

    int buf = 0;
    for (int tile = tile0; tile < NTILES; tile += gridDim.x) {
        const int ntile = tile + gridDim.x;
        const bool havenext = ntile < NTILES;

        // 1. stage next tile (fp32) into the alias region under the mma loop
        if (havenext) {
            const char* src = (const char*)(e + (size_t)ntile * TROWS * HH);
            #pragma unroll
            for (int q = 0; q < 10; q++) {
                int ch4 = tid + 256 * q;
                cpasync16(sb + ALIAS_OFF + ch4 * 16, src + ch4 * 16);
            }
            asm volatile("cp.async.commit_group;");
        }
        if (tid < TROWS) sIdx[tid] = edge_index[(size_t)tile * TROWS + tid];

        // 2. mma mainloop: D[80 x 128], 5 m-tiles per warp, single W term
        float acc[5][2][4];
        #pragma unroll
        for (int mt = 0; mt < 5; mt++)
            #pragma unroll
            for (int nt = 0; nt < 2; nt++)
                #pragma unroll
                for (int q = 0; q < 4; q++) acc[mt][nt][q] = 0.f;

        const uint32_t baseA = sb + SA_OFF + buf * ABUF_B;
        #pragma unroll
        for (int ks = 0; ks < 8; ks++) {
            #pragma unroll
            for (int mt = 0; mt < 5; mt++) {
                uint32_t a[4];
                int row = mt * 16 + lrow;
                uint32_t off = ((uint32_t)row << 8) +
                               (((uint32_t)((ks * 2 + lchk) ^ (row & 7))) << 4);
                ldsm4(baseA + off, a);
                mma16816(acc[mt][0], a, bh[ks][0], bh[ks][1]);
                mma16816(acc[mt][1], a, bh[ks][2], bh[ks][3]);
            }
        }

        // 3. drain stage into the other A buffer (frees the alias region)
        if (havenext) {
            asm volatile("cp.async.wait_group 0;" ::: "memory");
            char* dst = (char*)smem + SA_OFF + (buf ^ 1) * ABUF_B;
            const float4* stg = (const float4*)(smem + ALIAS_OFF);
            #pragma unroll
            for (int q = 0; q < 10; q++) {
                int ch4 = tid + 256 * q;
                cvtStoreF16(dst, ch4, stg[ch4]);
            }
        }
        __syncthreads();

        // 4. fragments -> logits (alias region, now free)
        #pragma unroll
        for (int mt = 0; mt < 5; mt++)
            #pragma unroll
            for (int nt = 0; nt < 2; nt++) {
                int r0 = mt * 16 + (l >> 2);
                int c0 = w * 16 + nt * 8 + 2 * (l & 3);
                *(float2*)(sLog + r0 * LSTRIDE + c0) =
                    make_float2(acc[mt][nt][0], acc[mt][nt][1]);
                *(float2*)(sLog + (r0 + 8) * LSTRIDE + c0) =
                    make_float2(acc[mt][nt][2], acc[mt][nt][3]);
            }
        __syncthreads();

        // 5. epilogue: softmax over 20 edges + gather; 2 (node,ch) per thread
        {
            const int j = tid & 127;
            #pragma unroll
            for (int h = 0; h < 2; h++) {
                const int tt = (tid >> 7) + 2 * h;
                float L[EE];
                #pragma unroll
                for (int i = 0; i < EE; i++)
                    L[i] = sLog[(tt * EE + i) * LSTRIDE + j];
                float m = L[0];
                #pragma unroll
                for (int i = 1; i < EE; i++) m = fmaxf(m, L[i]);
                float s = 0.f;
                #pragma unroll
                for (int i = 0; i < EE; i++) {
                    float ex = __expf(L[i] - m);
                    L[i] = ex;
                    s += ex;
                }
                const int node = tile * TNODES + tt;
                const int bbase = (node / NN) * NN;
                float accO = 0.f;
                #pragma unroll
                for (int i = 0; i < EE; i++) {
                    int rr = sIdx[tt * EE + i];
                    accO += L[i] * g_Vx[(size_t)(bbase + rr) * HH + j];
                }
                out[(size_t)node * HH + j] += accO * __fdividef(1.f, s);
            }
        }
        __syncthreads();
        buf ^= 1;
    }
}

// ---------------------------------------------------------------------------
extern "C" void kernel_launch(void* const* d_in, const int* in_sizes, int n_in,
                              void* d_out, int out_size)
{
    const float* x          = (const float*)d_in[0];
    const float* e          = (const float*)d_in[1];
    const float* Wu         = (const float*)d_in[2];
    const float* bu         = (const float*)d_in[3];
    const float* Wv         = (const float*)d_in[4];
    const float* bv         = (const float*)d_in[5];
    const float* We         = (const float*)d_in[6];
    const int*   edge_index = (const int*)d_in[8];
    float* out = (float*)d_out;

    int sms = 148;
    cudaDeviceGetAttribute(&sms, cudaDevAttrMultiProcessorCount, 0);

    cudaFuncSetAttribute(kA, cudaFuncAttributeMaxDynamicSharedMemorySize, KA_SMEM);
    cudaFuncSetAttribute(kB, cudaFuncAttributeMaxDynamicSharedMemorySize, SMEMB);

    kA<<<(BB * NN) / 128, 512, KA_SMEM>>>(x, Wu, bu, Wv, bv, out);
    kB<<<2 * sms, 256, SMEMB>>>(e, We, edge_index, out);
}